// round 4
// baseline (speedup 1.0000x reference)
#include <cuda_runtime.h>
#include <math.h>

#define BB 8192
#define TT 100
#define DD 44

typedef unsigned long long u64;

__device__ __forceinline__ void ffma2(u64& d, u64 a, u64 b) {
    asm("fma.rn.f32x2 %0, %1, %2, %0;" : "+l"(d) : "l"(a), "l"(b));
}
__device__ __forceinline__ void fadd2(u64& d, u64 a) {
    asm("add.rn.f32x2 %0, %0, %1;" : "+l"(d) : "l"(a));
}
__device__ __forceinline__ float2 unpack2(u64 v) {
    unsigned lo, hi;
    asm("mov.b64 {%0, %1}, %2;" : "=r"(lo), "=r"(hi) : "l"(v));
    return make_float2(__uint_as_float(lo), __uint_as_float(hi));
}
__device__ __forceinline__ float hadd2(u64 v) { float2 f = unpack2(v); return f.x + f.y; }
__device__ __forceinline__ u64 d2u(double d) { return (u64)__double_as_longlong(d); }
__device__ __forceinline__ u64 shflx(u64 v, int m) { return __shfl_xor_sync(0xffffffffu, v, m); }
__device__ __forceinline__ float fast_tanh(float x) { return 1.0f - 2.0f / (__expf(2.0f * x) + 1.0f); }
__device__ __forceinline__ float elu1(float x) { return x > 0.0f ? x : (__expf(x) - 1.0f); }

__device__ float g_z0[BB * 8];
__device__ float g_kl[BB];
__device__ float g_perb[BB];

// ---------------------------------------------------------------------------
// Kernel 1: reverse-time tanh RNN encoder.
// Block 128 thr = 4 warps; warp = 4 elements. lane = sub*8+jl.
// Weights K-pair packed; k-split over subs (28 k each of 112-padded);
// XOR-indexed reduce-scatter leaves elem `sub` at acc[0].
// ---------------------------------------------------------------------------
__global__ __launch_bounds__(128) void enc_kernel(
    const float* __restrict__ x, const float* __restrict__ mask,
    const float* __restrict__ eps,
    const float* __restrict__ Wi2h, const float* __restrict__ bi2h,
    const float* __restrict__ Wh2o, const float* __restrict__ bh2o)
{
    __shared__ __align__(16) float sWp[112 * 64];   // [kp][j][2]
    __shared__ __align__(16) float sWo[64 * 16];
    __shared__ __align__(16) float sb[64];
    __shared__ __align__(16) float sbo[16];
    __shared__ __align__(16) float sxh[16 * 116];   // per elem: x[0,44) h[44,108) pad0

    const int tid = threadIdx.x;
    for (int i = tid; i < 112 * 64; i += 128) {
        const int k = i >> 6, j = i & 63;
        sWp[((k >> 1) * 64 + j) * 2 + (k & 1)] = (k < 108) ? Wi2h[i] : 0.0f;
    }
    for (int i = tid; i < 1024; i += 128) sWo[i] = Wh2o[i];
    if (tid < 64) sb[tid] = bi2h[tid];
    if (tid < 16) sbo[tid] = bh2o[tid];
    for (int i = tid; i < 16 * 116; i += 128) sxh[i] = 0.0f;
    __syncthreads();

    const int lane = tid & 31, warp = tid >> 5;
    const int jl = lane & 7, sub = lane >> 3;
    const int eg = blockIdx.x * 16 + warp * 4;   // global element base of warp
    const int eb = warp * 4;                     // smem row base

    float* rp[4];
#pragma unroll
    for (int i = 0; i < 4; i++) rp[i] = &sxh[(eb + (sub ^ i)) * 116];
    float* myrow = rp[0];

    float br[8];
#pragma unroll
    for (int c = 0; c < 8; c++) br[c] = sb[8 * jl + c];

    // x/mask publish mapping: 4 elems * 44 = 176 = 5.5*32 -> 6 guarded rounds
    int pel[6], pdd[6];
#pragma unroll
    for (int r = 0; r < 6; r++) {
        const int idx = r * 32 + lane;
        pel[r] = idx / 44; pdd[r] = idx % 44;
    }
    float rx[6], rmk[6];
#pragma unroll
    for (int r = 0; r < 6; r++) {
        const int idx = r * 32 + lane;
        if (idx < 176) {
            const size_t off = (size_t)(eg + pel[r]) * TT * DD + (size_t)(TT - 1) * DD + pdd[r];
            rx[r] = x[off]; rmk[r] = mask[off];
        }
    }

    for (int t = TT - 1; t >= 0; --t) {
#pragma unroll
        for (int r = 0; r < 6; r++) {
            const int idx = r * 32 + lane;
            if (idx < 176) sxh[(eb + pel[r]) * 116 + pdd[r]] = rx[r] * rmk[r];
        }
        __syncwarp();
        if (t > 0) {
#pragma unroll
            for (int r = 0; r < 6; r++) {
                const int idx = r * 32 + lane;
                if (idx < 176) {
                    const size_t off = (size_t)(eg + pel[r]) * TT * DD + (size_t)(t - 1) * DD + pdd[r];
                    rx[r] = x[off]; rmk[r] = mask[off];
                }
            }
        }

        u64 acc[4][8];
#pragma unroll
        for (int i = 0; i < 4; i++)
#pragma unroll
            for (int c = 0; c < 8; c++) acc[i][c] = 0ull;

        const float* wb = &sWp[(sub * 14) * 128 + jl * 16];
#pragma unroll
        for (int kk = 0; kk < 14; kk++) {
            const double2* wp = (const double2*)(wb + kk * 128);
            const double2 wA = wp[0], wB = wp[1], wC = wp[2], wD = wp[3];
            const u64 w0 = d2u(wA.x), w1 = d2u(wA.y), w2 = d2u(wB.x), w3 = d2u(wB.y);
            const u64 w4 = d2u(wC.x), w5 = d2u(wC.y), w6 = d2u(wD.x), w7 = d2u(wD.y);
            const int k0 = (sub * 14 + kk) * 2;
#pragma unroll
            for (int i = 0; i < 4; i++) {
                const u64 v = d2u(*(const double*)&rp[i][k0]);
                ffma2(acc[i][0], w0, v); ffma2(acc[i][1], w1, v);
                ffma2(acc[i][2], w2, v); ffma2(acc[i][3], w3, v);
                ffma2(acc[i][4], w4, v); ffma2(acc[i][5], w5, v);
                ffma2(acc[i][6], w6, v); ffma2(acc[i][7], w7, v);
            }
        }
        // reduce-scatter: acc[0][c] <- full sum for element `sub`
#pragma unroll
        for (int c = 0; c < 8; c++) {
            fadd2(acc[0][c], shflx(acc[2][c], 16));
            fadd2(acc[1][c], shflx(acc[3][c], 16));
        }
#pragma unroll
        for (int c = 0; c < 8; c++) fadd2(acc[0][c], shflx(acc[1][c], 8));

        float hv[8];
#pragma unroll
        for (int c = 0; c < 8; c++) hv[c] = fast_tanh(hadd2(acc[0][c]) + br[c]);
        __syncwarp();
        float4* hw = (float4*)&myrow[44 + 8 * jl];
        hw[0] = make_float4(hv[0], hv[1], hv[2], hv[3]);
        hw[1] = make_float4(hv[4], hv[5], hv[6], hv[7]);
        __syncwarp();
    }

    // out = h_final @ Wh2o + bh2o ; lane (sub,jl): elem sub, output pair 2jl
    float o0 = sbo[2 * jl], o1 = sbo[2 * jl + 1];
#pragma unroll 8
    for (int k = 0; k < 64; k++) {
        const float v = myrow[44 + k];
        o0 += v * sWo[k * 16 + 2 * jl];
        o1 += v * sWo[k * 16 + 2 * jl + 1];
    }
    const float p0 = __shfl_xor_sync(0xffffffffu, o0, 4);
    const float p1 = __shfl_xor_sync(0xffffffffu, o1, 4);
    const int b = eg + sub;
    float kl = 0.0f;
    if (jl < 4) {
        const float2 ep = *(const float2*)&eps[b * 8 + 2 * jl];
        const float z0a = ep.x * __expf(0.5f * p0) + o0;
        const float z0b = ep.y * __expf(0.5f * p1) + o1;
        *(float2*)&g_z0[b * 8 + 2 * jl] = make_float2(z0a, z0b);
        kl = -0.5f * p0 + (__expf(p0) + o0 * o0) * 0.5f - 0.5f
           + -0.5f * p1 + (__expf(p1) + o1 * o1) * 0.5f - 0.5f;
    }
    kl += __shfl_xor_sync(0xffffffffu, kl, 1);
    kl += __shfl_xor_sync(0xffffffffu, kl, 2);
    if (jl == 0) g_kl[b] = kl;
}

// ---------------------------------------------------------------------------
// Kernel 2: RK4 latent ODE + decoder + Gaussian NLL.
// Row layout (stride 140): [0,8) z/ztmp  [8,72) h1/hd  [72,136) h2
// ---------------------------------------------------------------------------
__global__ __launch_bounds__(128) void ode_kernel(
    const float* __restrict__ x, const float* __restrict__ mask,
    const float* __restrict__ Wf1, const float* __restrict__ bf1,
    const float* __restrict__ Wf2, const float* __restrict__ bf2,
    const float* __restrict__ Wf3, const float* __restrict__ bf3,
    const float* __restrict__ Wd1, const float* __restrict__ bd1,
    const float* __restrict__ Wd2, const float* __restrict__ bd2)
{
    __shared__ __align__(16) float sWf1p[512], sWd1p[512];
    __shared__ __align__(16) float sWf2p[4096];
    __shared__ __align__(16) float sWd2p[32 * 96];
    __shared__ __align__(16) float sWf3T[8 * 64];
    __shared__ __align__(16) float sbf1[64], sbf2[64], sbf3[8], sbd1[64], sbd2[48];
    __shared__ __align__(16) float sv[16 * 140];

    const int tid = threadIdx.x;
    for (int i = tid; i < 512; i += 128) {
        const int k = i >> 6, j = i & 63;
        const int d = ((k >> 1) * 64 + j) * 2 + (k & 1);
        sWf1p[d] = Wf1[i]; sWd1p[d] = Wd1[i];
    }
    for (int i = tid; i < 4096; i += 128) {
        const int k = i >> 6, j = i & 63;
        sWf2p[((k >> 1) * 64 + j) * 2 + (k & 1)] = Wf2[i];
    }
    for (int i = tid; i < 3072; i += 128) {
        const int kp = i / 96, rem = i % 96, j = rem >> 1, par = rem & 1;
        const int k = 2 * kp + par;
        sWd2p[i] = (j < 44) ? Wd2[k * 44 + j] : 0.0f;
    }
    for (int i = tid; i < 512; i += 128) {
        const int k = i >> 3, j = i & 7;
        sWf3T[j * 64 + k] = Wf3[i];
    }
    if (tid < 64) { sbf1[tid] = bf1[tid]; sbf2[tid] = bf2[tid]; sbd1[tid] = bd1[tid]; }
    if (tid < 8)  sbf3[tid] = bf3[tid];
    if (tid < 48) sbd2[tid] = (tid < 44) ? bd2[tid] : 0.0f;
    __syncthreads();

    const int lane = tid & 31, warp = tid >> 5;
    const int jl = lane & 7, sub = lane >> 3;
    const int eg = blockIdx.x * 16 + warp * 4;
    const int eb = warp * 4;
    const int b = eg + sub;

    float* rp[4];
#pragma unroll
    for (int i = 0; i < 4; i++) rp[i] = &sv[(eb + (sub ^ i)) * 140];
    float* myrow = rp[0];

    float zr = g_z0[b * 8 + jl];
    myrow[jl] = zr;
    __syncwarp();

    const float dt = 1.0f / (float)(TT - 1);
    const float* xb = x    + (size_t)b * TT * DD + 6 * jl;
    const float* mb = mask + (size_t)b * TT * DD + 6 * jl;
    float sse = 0.0f;

    for (int t = 0; t < TT; t++) {
        // ---- decoder: hd = relu(z @ Wd1 + bd1), per-sub (G=1) ----
        {
            u64 a[8];
#pragma unroll
            for (int c = 0; c < 8; c++) a[c] = 0ull;
#pragma unroll
            for (int kp = 0; kp < 4; kp++) {
                const double2* wp = (const double2*)&sWd1p[kp * 128 + jl * 16];
                const double2 wA = wp[0], wB = wp[1], wC = wp[2], wD = wp[3];
                const u64 v = d2u(*(const double*)&myrow[kp * 2]);
                ffma2(a[0], d2u(wA.x), v); ffma2(a[1], d2u(wA.y), v);
                ffma2(a[2], d2u(wB.x), v); ffma2(a[3], d2u(wB.y), v);
                ffma2(a[4], d2u(wC.x), v); ffma2(a[5], d2u(wC.y), v);
                ffma2(a[6], d2u(wD.x), v); ffma2(a[7], d2u(wD.y), v);
            }
            float hv[8];
#pragma unroll
            for (int c = 0; c < 8; c++) hv[c] = fmaxf(hadd2(a[c]) + sbd1[8 * jl + c], 0.0f);
            __syncwarp();
            float4* hw = (float4*)&myrow[8 + 8 * jl];
            hw[0] = make_float4(hv[0], hv[1], hv[2], hv[3]);
            hw[1] = make_float4(hv[4], hv[5], hv[6], hv[7]);
            __syncwarp();
        }
        // ---- px = hd @ Wd2p + bd2p (48 cols), k-split + scatter; loss ----
        {
            u64 a[4][6];
#pragma unroll
            for (int i = 0; i < 4; i++)
#pragma unroll
                for (int c = 0; c < 6; c++) a[i][c] = 0ull;
#pragma unroll
            for (int kk = 0; kk < 8; kk++) {
                const int kp = sub * 8 + kk;
                const double2* wp = (const double2*)&sWd2p[kp * 96 + jl * 12];
                const double2 wA = wp[0], wB = wp[1], wC = wp[2];
                const u64 w0 = d2u(wA.x), w1 = d2u(wA.y), w2 = d2u(wB.x);
                const u64 w3 = d2u(wB.y), w4 = d2u(wC.x), w5 = d2u(wC.y);
#pragma unroll
                for (int i = 0; i < 4; i++) {
                    const u64 v = d2u(*(const double*)&rp[i][8 + kp * 2]);
                    ffma2(a[i][0], w0, v); ffma2(a[i][1], w1, v);
                    ffma2(a[i][2], w2, v); ffma2(a[i][3], w3, v);
                    ffma2(a[i][4], w4, v); ffma2(a[i][5], w5, v);
                }
            }
#pragma unroll
            for (int c = 0; c < 6; c++) {
                fadd2(a[0][c], shflx(a[2][c], 16));
                fadd2(a[1][c], shflx(a[3][c], 16));
            }
#pragma unroll
            for (int c = 0; c < 6; c++) fadd2(a[0][c], shflx(a[1][c], 8));

            const float* xt = xb + t * DD;
            const float* mt = mb + t * DD;
#pragma unroll
            for (int i = 0; i < 3; i++) {
                const int d0 = 6 * jl + 2 * i;
                if (d0 < 44) {
                    const float2 xv = *(const float2*)&xt[2 * i];
                    const float2 mv = *(const float2*)&mt[2 * i];
                    const float px0 = hadd2(a[0][2 * i])     + sbd2[d0];
                    const float px1 = hadd2(a[0][2 * i + 1]) + sbd2[d0 + 1];
                    float da = xv.x - px0, db = xv.y - px1;
                    da = (xv.x * mv.x != 0.0f) ? 0.0f : da;
                    db = (xv.y * mv.y != 0.0f) ? 0.0f : db;
                    sse += da * da + db * db;
                }
            }
        }

        // ---- RK4 step ----
        if (t < TT - 1) {
            float zac = zr;
#pragma unroll 1
            for (int s = 0; s < 4; s++) {
                const float wco = (s == 0 || s == 3) ? dt / 6.0f : dt / 3.0f;
                const float cco = (s == 2) ? dt : 0.5f * dt;
                // h1 = elu(zin @ Wf1 + bf1), per-sub
                {
                    u64 a[8];
#pragma unroll
                    for (int c = 0; c < 8; c++) a[c] = 0ull;
#pragma unroll
                    for (int kp = 0; kp < 4; kp++) {
                        const double2* wp = (const double2*)&sWf1p[kp * 128 + jl * 16];
                        const double2 wA = wp[0], wB = wp[1], wC = wp[2], wD = wp[3];
                        const u64 v = d2u(*(const double*)&myrow[kp * 2]);
                        ffma2(a[0], d2u(wA.x), v); ffma2(a[1], d2u(wA.y), v);
                        ffma2(a[2], d2u(wB.x), v); ffma2(a[3], d2u(wB.y), v);
                        ffma2(a[4], d2u(wC.x), v); ffma2(a[5], d2u(wC.y), v);
                        ffma2(a[6], d2u(wD.x), v); ffma2(a[7], d2u(wD.y), v);
                    }
                    float hv[8];
#pragma unroll
                    for (int c = 0; c < 8; c++) hv[c] = elu1(hadd2(a[c]) + sbf1[8 * jl + c]);
                    __syncwarp();
                    float4* hw = (float4*)&myrow[8 + 8 * jl];
                    hw[0] = make_float4(hv[0], hv[1], hv[2], hv[3]);
                    hw[1] = make_float4(hv[4], hv[5], hv[6], hv[7]);
                    __syncwarp();
                }
                // h2 = elu(h1 @ Wf2 + bf2), k-split + scatter
                {
                    u64 a[4][8];
#pragma unroll
                    for (int i = 0; i < 4; i++)
#pragma unroll
                        for (int c = 0; c < 8; c++) a[i][c] = 0ull;
#pragma unroll
                    for (int kk = 0; kk < 8; kk++) {
                        const int kp = sub * 8 + kk;
                        const double2* wp = (const double2*)&sWf2p[kp * 128 + jl * 16];
                        const double2 wA = wp[0], wB = wp[1], wC = wp[2], wD = wp[3];
                        const u64 w0 = d2u(wA.x), w1 = d2u(wA.y), w2 = d2u(wB.x), w3 = d2u(wB.y);
                        const u64 w4 = d2u(wC.x), w5 = d2u(wC.y), w6 = d2u(wD.x), w7 = d2u(wD.y);
#pragma unroll
                        for (int i = 0; i < 4; i++) {
                            const u64 v = d2u(*(const double*)&rp[i][8 + kp * 2]);
                            ffma2(a[i][0], w0, v); ffma2(a[i][1], w1, v);
                            ffma2(a[i][2], w2, v); ffma2(a[i][3], w3, v);
                            ffma2(a[i][4], w4, v); ffma2(a[i][5], w5, v);
                            ffma2(a[i][6], w6, v); ffma2(a[i][7], w7, v);
                        }
                    }
#pragma unroll
                    for (int c = 0; c < 8; c++) {
                        fadd2(a[0][c], shflx(a[2][c], 16));
                        fadd2(a[1][c], shflx(a[3][c], 16));
                    }
#pragma unroll
                    for (int c = 0; c < 8; c++) fadd2(a[0][c], shflx(a[1][c], 8));
                    float hv[8];
#pragma unroll
                    for (int c = 0; c < 8; c++) hv[c] = elu1(hadd2(a[0][c]) + sbf2[8 * jl + c]);
                    __syncwarp();
                    float4* hw = (float4*)&myrow[72 + 8 * jl];
                    hw[0] = make_float4(hv[0], hv[1], hv[2], hv[3]);
                    hw[1] = make_float4(hv[4], hv[5], hv[6], hv[7]);
                    __syncwarp();
                }
                // f[jl] = h2 @ Wf3T[jl] + bf3[jl], per-sub scalar
                float f;
                {
                    u64 aE = 0ull, aO = 0ull;
#pragma unroll
                    for (int kq = 0; kq < 16; kq++) {
                        const double2 w = *(const double2*)&sWf3T[jl * 64 + kq * 4];
                        const double2 v = *(const double2*)&myrow[72 + kq * 4];
                        ffma2(aE, d2u(w.x), d2u(v.x));
                        ffma2(aO, d2u(w.y), d2u(v.y));
                    }
                    f = hadd2(aE) + hadd2(aO) + sbf3[jl];
                }
                zac += wco * f;
                float zin;
                if (s < 3) zin = zr + cco * f;
                else { zr = zac; zin = zac; }
                myrow[jl] = zin;
                __syncwarp();
            }
        }
    }

    sse += __shfl_xor_sync(0xffffffffu, sse, 1);
    sse += __shfl_xor_sync(0xffffffffu, sse, 2);
    sse += __shfl_xor_sync(0xffffffffu, sse, 4);
    if (jl == 0) {
        const float nlv = 2.0f * logf(0.3f);
        const float l2p = logf(6.283185307179586f);
        const float logpx = -0.5f * ((float)(TT * DD) * (l2p + nlv) + sse / expf(nlv));
        g_perb[b] = -logpx + g_kl[b];
    }
}

// ---------------------------------------------------------------------------
__global__ void reduce_kernel(float* __restrict__ out)
{
    __shared__ float s[1024];
    const int tid = threadIdx.x;
    float v = 0.0f;
    for (int i = tid; i < BB; i += 1024) v += g_perb[i];
    s[tid] = v;
    __syncthreads();
    for (int st = 512; st > 0; st >>= 1) {
        if (tid < st) s[tid] += s[tid + st];
        __syncthreads();
    }
    if (tid == 0) out[0] = s[0] / (float)BB;
}

// ---------------------------------------------------------------------------
extern "C" void kernel_launch(void* const* d_in, const int* in_sizes, int n_in,
                              void* d_out, int out_size)
{
    const float* x    = (const float*)d_in[0];
    const float* mask = (const float*)d_in[1];
    const float* eps  = (const float*)d_in[2];
    const float* Wi2h = (const float*)d_in[3];
    const float* bi2h = (const float*)d_in[4];
    const float* Wh2o = (const float*)d_in[5];
    const float* bh2o = (const float*)d_in[6];
    const float* Wf1  = (const float*)d_in[7];
    const float* bf1  = (const float*)d_in[8];
    const float* Wf2  = (const float*)d_in[9];
    const float* bf2  = (const float*)d_in[10];
    const float* Wf3  = (const float*)d_in[11];
    const float* bf3  = (const float*)d_in[12];
    const float* Wd1  = (const float*)d_in[13];
    const float* bd1  = (const float*)d_in[14];
    const float* Wd2  = (const float*)d_in[15];
    const float* bd2  = (const float*)d_in[16];

    enc_kernel<<<BB / 16, 128>>>(x, mask, eps, Wi2h, bi2h, Wh2o, bh2o);
    ode_kernel<<<BB / 16, 128>>>(x, mask, Wf1, bf1, Wf2, bf2, Wf3, bf3,
                                 Wd1, bd1, Wd2, bd2);
    reduce_kernel<<<1, 1024>>>((float*)d_out);
}

// round 5
// speedup vs baseline: 1.0010x; 1.0010x over previous
#include <cuda_runtime.h>
#include <math.h>

#define BB 8192
#define TT 100
#define DD 44

typedef unsigned long long u64;

__device__ __forceinline__ void ffma2(u64& d, u64 a, u64 b) {
    asm("fma.rn.f32x2 %0, %1, %2, %0;" : "+l"(d) : "l"(a), "l"(b));
}
__device__ __forceinline__ void fadd2(u64& d, u64 a) {
    asm("add.rn.f32x2 %0, %0, %1;" : "+l"(d) : "l"(a));
}
__device__ __forceinline__ float2 unpack2(u64 v) {
    unsigned lo, hi;
    asm("mov.b64 {%0, %1}, %2;" : "=r"(lo), "=r"(hi) : "l"(v));
    return make_float2(__uint_as_float(lo), __uint_as_float(hi));
}
__device__ __forceinline__ float hadd2(u64 v) { float2 f = unpack2(v); return f.x + f.y; }
__device__ __forceinline__ u64 d2u(double d) { return (u64)__double_as_longlong(d); }
__device__ __forceinline__ u64 shflx(u64 v, int m) { return __shfl_xor_sync(0xffffffffu, v, m); }
__device__ __forceinline__ float fast_tanh(float x) { return 1.0f - 2.0f / (__expf(2.0f * x) + 1.0f); }
__device__ __forceinline__ float elu1(float x) { return x > 0.0f ? x : (__expf(x) - 1.0f); }

__device__ float g_z0[BB * 8];
__device__ float g_kl[BB];
__device__ float g_perb[BB];

// ---------------------------------------------------------------------------
// Kernel 1: reverse-time tanh RNN encoder.
// Block 128 thr = 4 warps; warp = 4 elements. lane = sub*8+jl.
// Weights K-pair packed; k-split over subs (28 k each of 112-padded);
// XOR-indexed reduce-scatter leaves elem `sub` at acc[0].
// ---------------------------------------------------------------------------
__global__ __launch_bounds__(128) void enc_kernel(
    const float* __restrict__ x, const float* __restrict__ mask,
    const float* __restrict__ eps,
    const float* __restrict__ Wi2h, const float* __restrict__ bi2h,
    const float* __restrict__ Wh2o, const float* __restrict__ bh2o)
{
    __shared__ __align__(16) float sWp[112 * 64];   // [kp][j][2]
    __shared__ __align__(16) float sWo[64 * 16];
    __shared__ __align__(16) float sb[64];
    __shared__ __align__(16) float sbo[16];
    __shared__ __align__(16) float sxh[16 * 116];   // per elem: x[0,44) h[44,108) pad0

    const int tid = threadIdx.x;
    for (int i = tid; i < 112 * 64; i += 128) {
        const int k = i >> 6, j = i & 63;
        sWp[((k >> 1) * 64 + j) * 2 + (k & 1)] = (k < 108) ? Wi2h[i] : 0.0f;
    }
    for (int i = tid; i < 1024; i += 128) sWo[i] = Wh2o[i];
    if (tid < 64) sb[tid] = bi2h[tid];
    if (tid < 16) sbo[tid] = bh2o[tid];
    for (int i = tid; i < 16 * 116; i += 128) sxh[i] = 0.0f;
    __syncthreads();

    const int lane = tid & 31, warp = tid >> 5;
    const int jl = lane & 7, sub = lane >> 3;
    const int eg = blockIdx.x * 16 + warp * 4;   // global element base of warp
    const int eb = warp * 4;                     // smem row base

    float* rp[4];
#pragma unroll
    for (int i = 0; i < 4; i++) rp[i] = &sxh[(eb + (sub ^ i)) * 116];
    float* myrow = rp[0];

    float br[8];
#pragma unroll
    for (int c = 0; c < 8; c++) br[c] = sb[8 * jl + c];

    // x/mask publish mapping: 4 elems * 44 = 176 = 5.5*32 -> 6 guarded rounds
    int pel[6], pdd[6];
#pragma unroll
    for (int r = 0; r < 6; r++) {
        const int idx = r * 32 + lane;
        pel[r] = idx / 44; pdd[r] = idx % 44;
    }
    float rx[6], rmk[6];
#pragma unroll
    for (int r = 0; r < 6; r++) {
        const int idx = r * 32 + lane;
        if (idx < 176) {
            const size_t off = (size_t)(eg + pel[r]) * TT * DD + (size_t)(TT - 1) * DD + pdd[r];
            rx[r] = x[off]; rmk[r] = mask[off];
        }
    }

    for (int t = TT - 1; t >= 0; --t) {
#pragma unroll
        for (int r = 0; r < 6; r++) {
            const int idx = r * 32 + lane;
            if (idx < 176) sxh[(eb + pel[r]) * 116 + pdd[r]] = rx[r] * rmk[r];
        }
        __syncwarp();
        if (t > 0) {
#pragma unroll
            for (int r = 0; r < 6; r++) {
                const int idx = r * 32 + lane;
                if (idx < 176) {
                    const size_t off = (size_t)(eg + pel[r]) * TT * DD + (size_t)(t - 1) * DD + pdd[r];
                    rx[r] = x[off]; rmk[r] = mask[off];
                }
            }
        }

        u64 acc[4][8];
#pragma unroll
        for (int i = 0; i < 4; i++)
#pragma unroll
            for (int c = 0; c < 8; c++) acc[i][c] = 0ull;

        const float* wb = &sWp[(sub * 14) * 128 + jl * 16];
#pragma unroll
        for (int kk = 0; kk < 14; kk++) {
            const double2* wp = (const double2*)(wb + kk * 128);
            const double2 wA = wp[0], wB = wp[1], wC = wp[2], wD = wp[3];
            const u64 w0 = d2u(wA.x), w1 = d2u(wA.y), w2 = d2u(wB.x), w3 = d2u(wB.y);
            const u64 w4 = d2u(wC.x), w5 = d2u(wC.y), w6 = d2u(wD.x), w7 = d2u(wD.y);
            const int k0 = (sub * 14 + kk) * 2;
#pragma unroll
            for (int i = 0; i < 4; i++) {
                const u64 v = d2u(*(const double*)&rp[i][k0]);
                ffma2(acc[i][0], w0, v); ffma2(acc[i][1], w1, v);
                ffma2(acc[i][2], w2, v); ffma2(acc[i][3], w3, v);
                ffma2(acc[i][4], w4, v); ffma2(acc[i][5], w5, v);
                ffma2(acc[i][6], w6, v); ffma2(acc[i][7], w7, v);
            }
        }
        // reduce-scatter: acc[0][c] <- full sum for element `sub`
#pragma unroll
        for (int c = 0; c < 8; c++) {
            fadd2(acc[0][c], shflx(acc[2][c], 16));
            fadd2(acc[1][c], shflx(acc[3][c], 16));
        }
#pragma unroll
        for (int c = 0; c < 8; c++) fadd2(acc[0][c], shflx(acc[1][c], 8));

        float hv[8];
#pragma unroll
        for (int c = 0; c < 8; c++) hv[c] = fast_tanh(hadd2(acc[0][c]) + br[c]);
        __syncwarp();
        float4* hw = (float4*)&myrow[44 + 8 * jl];
        hw[0] = make_float4(hv[0], hv[1], hv[2], hv[3]);
        hw[1] = make_float4(hv[4], hv[5], hv[6], hv[7]);
        __syncwarp();
    }

    // out = h_final @ Wh2o + bh2o ; lane (sub,jl): elem sub, output pair 2jl
    float o0 = sbo[2 * jl], o1 = sbo[2 * jl + 1];
#pragma unroll 8
    for (int k = 0; k < 64; k++) {
        const float v = myrow[44 + k];
        o0 += v * sWo[k * 16 + 2 * jl];
        o1 += v * sWo[k * 16 + 2 * jl + 1];
    }
    const float p0 = __shfl_xor_sync(0xffffffffu, o0, 4);
    const float p1 = __shfl_xor_sync(0xffffffffu, o1, 4);
    const int b = eg + sub;
    float kl = 0.0f;
    if (jl < 4) {
        const float2 ep = *(const float2*)&eps[b * 8 + 2 * jl];
        const float z0a = ep.x * __expf(0.5f * p0) + o0;
        const float z0b = ep.y * __expf(0.5f * p1) + o1;
        *(float2*)&g_z0[b * 8 + 2 * jl] = make_float2(z0a, z0b);
        kl = -0.5f * p0 + (__expf(p0) + o0 * o0) * 0.5f - 0.5f
           + -0.5f * p1 + (__expf(p1) + o1 * o1) * 0.5f - 0.5f;
    }
    kl += __shfl_xor_sync(0xffffffffu, kl, 1);
    kl += __shfl_xor_sync(0xffffffffu, kl, 2);
    if (jl == 0) g_kl[b] = kl;
}

// ---------------------------------------------------------------------------
// Kernel 2: RK4 latent ODE + decoder + Gaussian NLL.
// Row layout (stride 140): [0,8) z/ztmp  [8,72) h1/hd  [72,136) h2
// ---------------------------------------------------------------------------
__global__ __launch_bounds__(128) void ode_kernel(
    const float* __restrict__ x, const float* __restrict__ mask,
    const float* __restrict__ Wf1, const float* __restrict__ bf1,
    const float* __restrict__ Wf2, const float* __restrict__ bf2,
    const float* __restrict__ Wf3, const float* __restrict__ bf3,
    const float* __restrict__ Wd1, const float* __restrict__ bd1,
    const float* __restrict__ Wd2, const float* __restrict__ bd2)
{
    __shared__ __align__(16) float sWf1p[512], sWd1p[512];
    __shared__ __align__(16) float sWf2p[4096];
    __shared__ __align__(16) float sWd2p[32 * 96];
    __shared__ __align__(16) float sWf3T[8 * 64];
    __shared__ __align__(16) float sbf1[64], sbf2[64], sbf3[8], sbd1[64], sbd2[48];
    __shared__ __align__(16) float sv[16 * 140];

    const int tid = threadIdx.x;
    for (int i = tid; i < 512; i += 128) {
        const int k = i >> 6, j = i & 63;
        const int d = ((k >> 1) * 64 + j) * 2 + (k & 1);
        sWf1p[d] = Wf1[i]; sWd1p[d] = Wd1[i];
    }
    for (int i = tid; i < 4096; i += 128) {
        const int k = i >> 6, j = i & 63;
        sWf2p[((k >> 1) * 64 + j) * 2 + (k & 1)] = Wf2[i];
    }
    for (int i = tid; i < 3072; i += 128) {
        const int kp = i / 96, rem = i % 96, j = rem >> 1, par = rem & 1;
        const int k = 2 * kp + par;
        sWd2p[i] = (j < 44) ? Wd2[k * 44 + j] : 0.0f;
    }
    for (int i = tid; i < 512; i += 128) {
        const int k = i >> 3, j = i & 7;
        sWf3T[j * 64 + k] = Wf3[i];
    }
    if (tid < 64) { sbf1[tid] = bf1[tid]; sbf2[tid] = bf2[tid]; sbd1[tid] = bd1[tid]; }
    if (tid < 8)  sbf3[tid] = bf3[tid];
    if (tid < 48) sbd2[tid] = (tid < 44) ? bd2[tid] : 0.0f;
    __syncthreads();

    const int lane = tid & 31, warp = tid >> 5;
    const int jl = lane & 7, sub = lane >> 3;
    const int eg = blockIdx.x * 16 + warp * 4;
    const int eb = warp * 4;
    const int b = eg + sub;

    float* rp[4];
#pragma unroll
    for (int i = 0; i < 4; i++) rp[i] = &sv[(eb + (sub ^ i)) * 140];
    float* myrow = rp[0];

    float zr = g_z0[b * 8 + jl];
    myrow[jl] = zr;
    __syncwarp();

    const float dt = 1.0f / (float)(TT - 1);
    const float* xb = x    + (size_t)b * TT * DD + 6 * jl;
    const float* mb = mask + (size_t)b * TT * DD + 6 * jl;
    float sse = 0.0f;

    for (int t = 0; t < TT; t++) {
        // ---- decoder: hd = relu(z @ Wd1 + bd1), per-sub (G=1) ----
        {
            u64 a[8];
#pragma unroll
            for (int c = 0; c < 8; c++) a[c] = 0ull;
#pragma unroll
            for (int kp = 0; kp < 4; kp++) {
                const double2* wp = (const double2*)&sWd1p[kp * 128 + jl * 16];
                const double2 wA = wp[0], wB = wp[1], wC = wp[2], wD = wp[3];
                const u64 v = d2u(*(const double*)&myrow[kp * 2]);
                ffma2(a[0], d2u(wA.x), v); ffma2(a[1], d2u(wA.y), v);
                ffma2(a[2], d2u(wB.x), v); ffma2(a[3], d2u(wB.y), v);
                ffma2(a[4], d2u(wC.x), v); ffma2(a[5], d2u(wC.y), v);
                ffma2(a[6], d2u(wD.x), v); ffma2(a[7], d2u(wD.y), v);
            }
            float hv[8];
#pragma unroll
            for (int c = 0; c < 8; c++) hv[c] = fmaxf(hadd2(a[c]) + sbd1[8 * jl + c], 0.0f);
            __syncwarp();
            float4* hw = (float4*)&myrow[8 + 8 * jl];
            hw[0] = make_float4(hv[0], hv[1], hv[2], hv[3]);
            hw[1] = make_float4(hv[4], hv[5], hv[6], hv[7]);
            __syncwarp();
        }
        // ---- px = hd @ Wd2p + bd2p (48 cols), k-split + scatter; loss ----
        {
            u64 a[4][6];
#pragma unroll
            for (int i = 0; i < 4; i++)
#pragma unroll
                for (int c = 0; c < 6; c++) a[i][c] = 0ull;
#pragma unroll
            for (int kk = 0; kk < 8; kk++) {
                const int kp = sub * 8 + kk;
                const double2* wp = (const double2*)&sWd2p[kp * 96 + jl * 12];
                const double2 wA = wp[0], wB = wp[1], wC = wp[2];
                const u64 w0 = d2u(wA.x), w1 = d2u(wA.y), w2 = d2u(wB.x);
                const u64 w3 = d2u(wB.y), w4 = d2u(wC.x), w5 = d2u(wC.y);
#pragma unroll
                for (int i = 0; i < 4; i++) {
                    const u64 v = d2u(*(const double*)&rp[i][8 + kp * 2]);
                    ffma2(a[i][0], w0, v); ffma2(a[i][1], w1, v);
                    ffma2(a[i][2], w2, v); ffma2(a[i][3], w3, v);
                    ffma2(a[i][4], w4, v); ffma2(a[i][5], w5, v);
                }
            }
#pragma unroll
            for (int c = 0; c < 6; c++) {
                fadd2(a[0][c], shflx(a[2][c], 16));
                fadd2(a[1][c], shflx(a[3][c], 16));
            }
#pragma unroll
            for (int c = 0; c < 6; c++) fadd2(a[0][c], shflx(a[1][c], 8));

            const float* xt = xb + t * DD;
            const float* mt = mb + t * DD;
#pragma unroll
            for (int i = 0; i < 3; i++) {
                const int d0 = 6 * jl + 2 * i;
                if (d0 < 44) {
                    const float2 xv = *(const float2*)&xt[2 * i];
                    const float2 mv = *(const float2*)&mt[2 * i];
                    const float px0 = hadd2(a[0][2 * i])     + sbd2[d0];
                    const float px1 = hadd2(a[0][2 * i + 1]) + sbd2[d0 + 1];
                    float da = xv.x - px0, db = xv.y - px1;
                    da = (xv.x * mv.x != 0.0f) ? 0.0f : da;
                    db = (xv.y * mv.y != 0.0f) ? 0.0f : db;
                    sse += da * da + db * db;
                }
            }
        }

        // ---- RK4 step ----
        if (t < TT - 1) {
            float zac = zr;
#pragma unroll 1
            for (int s = 0; s < 4; s++) {
                const float wco = (s == 0 || s == 3) ? dt / 6.0f : dt / 3.0f;
                const float cco = (s == 2) ? dt : 0.5f * dt;
                // h1 = elu(zin @ Wf1 + bf1), per-sub
                {
                    u64 a[8];
#pragma unroll
                    for (int c = 0; c < 8; c++) a[c] = 0ull;
#pragma unroll
                    for (int kp = 0; kp < 4; kp++) {
                        const double2* wp = (const double2*)&sWf1p[kp * 128 + jl * 16];
                        const double2 wA = wp[0], wB = wp[1], wC = wp[2], wD = wp[3];
                        const u64 v = d2u(*(const double*)&myrow[kp * 2]);
                        ffma2(a[0], d2u(wA.x), v); ffma2(a[1], d2u(wA.y), v);
                        ffma2(a[2], d2u(wB.x), v); ffma2(a[3], d2u(wB.y), v);
                        ffma2(a[4], d2u(wC.x), v); ffma2(a[5], d2u(wC.y), v);
                        ffma2(a[6], d2u(wD.x), v); ffma2(a[7], d2u(wD.y), v);
                    }
                    float hv[8];
#pragma unroll
                    for (int c = 0; c < 8; c++) hv[c] = elu1(hadd2(a[c]) + sbf1[8 * jl + c]);
                    __syncwarp();
                    float4* hw = (float4*)&myrow[8 + 8 * jl];
                    hw[0] = make_float4(hv[0], hv[1], hv[2], hv[3]);
                    hw[1] = make_float4(hv[4], hv[5], hv[6], hv[7]);
                    __syncwarp();
                }
                // h2 = elu(h1 @ Wf2 + bf2), k-split + scatter
                {
                    u64 a[4][8];
#pragma unroll
                    for (int i = 0; i < 4; i++)
#pragma unroll
                        for (int c = 0; c < 8; c++) a[i][c] = 0ull;
#pragma unroll
                    for (int kk = 0; kk < 8; kk++) {
                        const int kp = sub * 8 + kk;
                        const double2* wp = (const double2*)&sWf2p[kp * 128 + jl * 16];
                        const double2 wA = wp[0], wB = wp[1], wC = wp[2], wD = wp[3];
                        const u64 w0 = d2u(wA.x), w1 = d2u(wA.y), w2 = d2u(wB.x), w3 = d2u(wB.y);
                        const u64 w4 = d2u(wC.x), w5 = d2u(wC.y), w6 = d2u(wD.x), w7 = d2u(wD.y);
#pragma unroll
                        for (int i = 0; i < 4; i++) {
                            const u64 v = d2u(*(const double*)&rp[i][8 + kp * 2]);
                            ffma2(a[i][0], w0, v); ffma2(a[i][1], w1, v);
                            ffma2(a[i][2], w2, v); ffma2(a[i][3], w3, v);
                            ffma2(a[i][4], w4, v); ffma2(a[i][5], w5, v);
                            ffma2(a[i][6], w6, v); ffma2(a[i][7], w7, v);
                        }
                    }
#pragma unroll
                    for (int c = 0; c < 8; c++) {
                        fadd2(a[0][c], shflx(a[2][c], 16));
                        fadd2(a[1][c], shflx(a[3][c], 16));
                    }
#pragma unroll
                    for (int c = 0; c < 8; c++) fadd2(a[0][c], shflx(a[1][c], 8));
                    float hv[8];
#pragma unroll
                    for (int c = 0; c < 8; c++) hv[c] = elu1(hadd2(a[0][c]) + sbf2[8 * jl + c]);
                    __syncwarp();
                    float4* hw = (float4*)&myrow[72 + 8 * jl];
                    hw[0] = make_float4(hv[0], hv[1], hv[2], hv[3]);
                    hw[1] = make_float4(hv[4], hv[5], hv[6], hv[7]);
                    __syncwarp();
                }
                // f[jl] = h2 @ Wf3T[jl] + bf3[jl], per-sub scalar
                float f;
                {
                    u64 aE = 0ull, aO = 0ull;
#pragma unroll
                    for (int kq = 0; kq < 16; kq++) {
                        const double2 w = *(const double2*)&sWf3T[jl * 64 + kq * 4];
                        const double2 v = *(const double2*)&myrow[72 + kq * 4];
                        ffma2(aE, d2u(w.x), d2u(v.x));
                        ffma2(aO, d2u(w.y), d2u(v.y));
                    }
                    f = hadd2(aE) + hadd2(aO) + sbf3[jl];
                }
                zac += wco * f;
                float zin;
                if (s < 3) zin = zr + cco * f;
                else { zr = zac; zin = zac; }
                myrow[jl] = zin;
                __syncwarp();
            }
        }
    }

    sse += __shfl_xor_sync(0xffffffffu, sse, 1);
    sse += __shfl_xor_sync(0xffffffffu, sse, 2);
    sse += __shfl_xor_sync(0xffffffffu, sse, 4);
    if (jl == 0) {
        const float nlv = 2.0f * logf(0.3f);
        const float l2p = logf(6.283185307179586f);
        const float logpx = -0.5f * ((float)(TT * DD) * (l2p + nlv) + sse / expf(nlv));
        g_perb[b] = -logpx + g_kl[b];
    }
}

// ---------------------------------------------------------------------------
__global__ void reduce_kernel(float* __restrict__ out)
{
    __shared__ float s[1024];
    const int tid = threadIdx.x;
    float v = 0.0f;
    for (int i = tid; i < BB; i += 1024) v += g_perb[i];
    s[tid] = v;
    __syncthreads();
    for (int st = 512; st > 0; st >>= 1) {
        if (tid < st) s[tid] += s[tid + st];
        __syncthreads();
    }
    if (tid == 0) out[0] = s[0] / (float)BB;
}

// ---------------------------------------------------------------------------
extern "C" void kernel_launch(void* const* d_in, const int* in_sizes, int n_in,
                              void* d_out, int out_size)
{
    const float* x    = (const float*)d_in[0];
    const float* mask = (const float*)d_in[1];
    const float* eps  = (const float*)d_in[2];
    const float* Wi2h = (const float*)d_in[3];
    const float* bi2h = (const float*)d_in[4];
    const float* Wh2o = (const float*)d_in[5];
    const float* bh2o = (const float*)d_in[6];
    const float* Wf1  = (const float*)d_in[7];
    const float* bf1  = (const float*)d_in[8];
    const float* Wf2  = (const float*)d_in[9];
    const float* bf2  = (const float*)d_in[10];
    const float* Wf3  = (const float*)d_in[11];
    const float* bf3  = (const float*)d_in[12];
    const float* Wd1  = (const float*)d_in[13];
    const float* bd1  = (const float*)d_in[14];
    const float* Wd2  = (const float*)d_in[15];
    const float* bd2  = (const float*)d_in[16];

    enc_kernel<<<BB / 16, 128>>>(x, mask, eps, Wi2h, bi2h, Wh2o, bh2o);
    ode_kernel<<<BB / 16, 128>>>(x, mask, Wf1, bf1, Wf2, bf2, Wf3, bf3,
                                 Wd1, bd1, Wd2, bd2);
    reduce_kernel<<<1, 1024>>>((float*)d_out);
}

// round 6
// speedup vs baseline: 3.3593x; 3.3558x over previous
#include <cuda_runtime.h>
#include <math.h>
#define BB 8192
#define TT 100
#define DD 44
typedef unsigned long long u64;

__device__ __forceinline__ void ffma2(u64& d, u64 a, u64 b) {
    asm("fma.rn.f32x2 %0, %1, %2, %0;" : "+l"(d) : "l"(a), "l"(b));
}
__device__ __forceinline__ float2 up2(u64 v) {
    unsigned lo, hi;
    asm("mov.b64 {%0, %1}, %2;" : "=r"(lo), "=r"(hi) : "l"(v));
    return make_float2(__uint_as_float(lo), __uint_as_float(hi));
}
__device__ __forceinline__ float hadd2(u64 v) { float2 f = up2(v); return f.x + f.y; }
__device__ __forceinline__ u64 d2u(double d) { return (u64)__double_as_longlong(d); }
__device__ __forceinline__ float ftanh(float x) { return 1.0f - __fdividef(2.0f, __expf(2.0f * x) + 1.0f); }
__device__ __forceinline__ float elu1(float x) { return x > 0.f ? x : (__expf(x) - 1.f); }

__device__ float g_z0[BB * 8];
__device__ float g_kl[BB];
__device__ float g_perb[BB];

// Shared GEMV: N=64, K=4*K4. Warp: 8 elems, lane owns cols (2l,2l+1).
// W packed [kp][j][2] (128 floats per kp). ACT: 0=relu, 1=elu.
template <int K4, int ACT>
__device__ __forceinline__ void gemv64(const float* __restrict__ W,
                                       float* const* row, int so, int dO,
                                       float ba, float bb, int lane)
{
    u64 aA[8], aB[8];
#pragma unroll
    for (int e = 0; e < 8; e++) { aA[e] = 0ull; aB[e] = 0ull; }
#pragma unroll 2
    for (int kq = 0; kq < K4; kq++) {
        const double2 wA = *(const double2*)&W[(2 * kq) * 128 + 4 * lane];
        const double2 wB = *(const double2*)&W[(2 * kq + 1) * 128 + 4 * lane];
        const u64 w0 = d2u(wA.x), w1 = d2u(wA.y), w2 = d2u(wB.x), w3 = d2u(wB.y);
#pragma unroll
        for (int e = 0; e < 8; e++) {
            const double2 vv = *(const double2*)&row[e][so + 4 * kq];
            const u64 v0 = d2u(vv.x), v1 = d2u(vv.y);
            ffma2(aA[e], w0, v0); ffma2(aB[e], w1, v0);
            ffma2(aA[e], w2, v1); ffma2(aB[e], w3, v1);
        }
    }
    __syncwarp();
#pragma unroll
    for (int e = 0; e < 8; e++) {
        float u = hadd2(aA[e]) + ba, v = hadd2(aB[e]) + bb;
        if (ACT == 0) { u = fmaxf(u, 0.f); v = fmaxf(v, 0.f); }
        else          { u = elu1(u);       v = elu1(v); }
        *(float2*)&row[e][dO + 2 * lane] = make_float2(u, v);
    }
    __syncwarp();
}

// ---------------------------------------------------------------------------
__global__ __launch_bounds__(64) void enc_kernel(
    const float* __restrict__ x, const float* __restrict__ mask,
    const float* __restrict__ eps,
    const float* __restrict__ Wi2h, const float* __restrict__ bi2h,
    const float* __restrict__ Wh2o, const float* __restrict__ bh2o)
{
    __shared__ __align__(16) float sWp[54 * 128];   // [kp][j][2], K=108
    __shared__ __align__(16) float sWoP[32 * 32];   // [kp][o][2], K=64,N=16
    __shared__ __align__(16) float sxh[16 * 112];   // x[0,44) h[44,108)

    const int tid = threadIdx.x;
    for (int i = tid; i < 108 * 64; i += 64) {
        const int k = i >> 6, j = i & 63;
        sWp[(k >> 1) * 128 + j * 2 + (k & 1)] = Wi2h[i];
    }
    for (int i = tid; i < 1024; i += 64) {
        const int k = i >> 4, o = i & 15;
        sWoP[(k >> 1) * 32 + o * 2 + (k & 1)] = Wh2o[i];
    }
    for (int i = tid; i < 16 * 112; i += 64) sxh[i] = 0.f;
    __syncthreads();

    const int lane = tid & 31, warp = tid >> 5;
    const int eg = blockIdx.x * 16 + warp * 8, eb = warp * 8;
    float* row[8];
#pragma unroll
    for (int e = 0; e < 8; e++) row[e] = &sxh[(eb + e) * 112];

    const float bia = __ldg(&bi2h[2 * lane]), bib = __ldg(&bi2h[2 * lane + 1]);

    float rx[11], rm[11];
#pragma unroll
    for (int r = 0; r < 11; r++) {
        const int idx = r * 32 + lane;
        const size_t off = (size_t)(eg + idx / 44) * TT * DD + (size_t)(TT - 1) * DD + idx % 44;
        rx[r] = x[off]; rm[r] = mask[off];
    }

#pragma unroll 1
    for (int t = TT - 1; t >= 0; --t) {
#pragma unroll
        for (int r = 0; r < 11; r++) {
            const int idx = r * 32 + lane;
            sxh[(eb + idx / 44) * 112 + idx % 44] = rx[r] * rm[r];
        }
        __syncwarp();
        if (t > 0) {
#pragma unroll
            for (int r = 0; r < 11; r++) {
                const int idx = r * 32 + lane;
                const size_t off = (size_t)(eg + idx / 44) * TT * DD + (size_t)(t - 1) * DD + idx % 44;
                rx[r] = x[off]; rm[r] = mask[off];
            }
        }
        u64 aA[8], aB[8];
#pragma unroll
        for (int e = 0; e < 8; e++) { aA[e] = 0ull; aB[e] = 0ull; }
#pragma unroll 3
        for (int kq = 0; kq < 27; kq++) {
            const double2 wA = *(const double2*)&sWp[(2 * kq) * 128 + 4 * lane];
            const double2 wB = *(const double2*)&sWp[(2 * kq + 1) * 128 + 4 * lane];
            const u64 w0 = d2u(wA.x), w1 = d2u(wA.y), w2 = d2u(wB.x), w3 = d2u(wB.y);
#pragma unroll
            for (int e = 0; e < 8; e++) {
                const double2 vv = *(const double2*)&row[e][4 * kq];
                const u64 v0 = d2u(vv.x), v1 = d2u(vv.y);
                ffma2(aA[e], w0, v0); ffma2(aB[e], w1, v0);
                ffma2(aA[e], w2, v1); ffma2(aB[e], w3, v1);
            }
        }
        __syncwarp();
#pragma unroll
        for (int e = 0; e < 8; e++)
            *(float2*)&row[e][44 + 2 * lane] =
                make_float2(ftanh(hadd2(aA[e]) + bia), ftanh(hadd2(aB[e]) + bib));
        __syncwarp();
    }

    // projection: lane -> elem e=lane>>2, outputs 4q..4q+3
    const int e = lane >> 2, q = lane & 3;
    const float* re = row[e];
    u64 o0 = 0, o1 = 0, o2 = 0, o3 = 0;
#pragma unroll 4
    for (int kp = 0; kp < 32; kp++) {
        const double2 wL = *(const double2*)&sWoP[kp * 32 + 8 * q];
        const double2 wH = *(const double2*)&sWoP[kp * 32 + 8 * q + 4];
        const u64 v = d2u(*(const double*)&re[44 + 2 * kp]);
        ffma2(o0, d2u(wL.x), v); ffma2(o1, d2u(wL.y), v);
        ffma2(o2, d2u(wH.x), v); ffma2(o3, d2u(wH.y), v);
    }
    float s0 = hadd2(o0) + __ldg(&bh2o[4 * q]);
    float s1 = hadd2(o1) + __ldg(&bh2o[4 * q + 1]);
    float s2 = hadd2(o2) + __ldg(&bh2o[4 * q + 2]);
    float s3 = hadd2(o3) + __ldg(&bh2o[4 * q + 3]);
    const float t0 = __shfl_xor_sync(0xffffffffu, s0, 2);
    const float t1 = __shfl_xor_sync(0xffffffffu, s1, 2);
    const float t2 = __shfl_xor_sync(0xffffffffu, s2, 2);
    const float t3 = __shfl_xor_sync(0xffffffffu, s3, 2);
    const int b = eg + e;
    float kl = 0.f;
    if (q < 2) {   // s = mean(4q+c), t = logvar(4q+c)
        const float4 ep = *(const float4*)&eps[b * 8 + 4 * q];
        float4 z;
        z.x = ep.x * __expf(0.5f * t0) + s0;
        z.y = ep.y * __expf(0.5f * t1) + s1;
        z.z = ep.z * __expf(0.5f * t2) + s2;
        z.w = ep.w * __expf(0.5f * t3) + s3;
        *(float4*)&g_z0[b * 8 + 4 * q] = z;
        kl = -0.5f * t0 + (__expf(t0) + s0 * s0) * 0.5f - 0.5f
           + -0.5f * t1 + (__expf(t1) + s1 * s1) * 0.5f - 0.5f
           + -0.5f * t2 + (__expf(t2) + s2 * s2) * 0.5f - 0.5f
           + -0.5f * t3 + (__expf(t3) + s3 * s3) * 0.5f - 0.5f;
    }
    kl += __shfl_xor_sync(0xffffffffu, kl, 1);
    if (q == 0) g_kl[b] = kl;
}

// ---------------------------------------------------------------------------
// ode: warp = 8 elems; row stride 140: z[0,8) h1[8,72) h2[72,136)
__global__ __launch_bounds__(64) void ode_kernel(
    const float* __restrict__ x, const float* __restrict__ mask,
    const float* __restrict__ Wf1, const float* __restrict__ bf1,
    const float* __restrict__ Wf2, const float* __restrict__ bf2,
    const float* __restrict__ Wf3, const float* __restrict__ bf3,
    const float* __restrict__ Wd1, const float* __restrict__ bd1,
    const float* __restrict__ Wd2, const float* __restrict__ bd2)
{
    __shared__ __align__(16) float sWd1p[4 * 128], sWf1p[4 * 128];
    __shared__ __align__(16) float sWf2p[32 * 128], sWd2p[32 * 128];
    __shared__ __align__(16) float sWf3p[32 * 16];
    __shared__ __align__(16) float sv[16 * 140];

    const int tid = threadIdx.x;
    for (int i = tid; i < 512; i += 64) {
        const int k = i >> 6, j = i & 63;
        const int d = (k >> 1) * 128 + j * 2 + (k & 1);
        sWd1p[d] = Wd1[i]; sWf1p[d] = Wf1[i];
    }
    for (int i = tid; i < 4096; i += 64) {
        const int k = i >> 6, j = i & 63;
        const int d = (k >> 1) * 128 + j * 2 + (k & 1);
        sWf2p[d] = Wf2[i];
        sWd2p[d] = (j < 44) ? Wd2[k * 44 + j] : 0.f;
    }
    for (int i = tid; i < 512; i += 64) {
        const int k = i >> 3, j = i & 7;
        sWf3p[(k >> 1) * 16 + j * 2 + (k & 1)] = Wf3[i];
    }
    __syncthreads();

    const int lane = tid & 31, warp = tid >> 5;
    const int eg = blockIdx.x * 16 + warp * 8, eb = warp * 8;
    float* row[8];
#pragma unroll
    for (int e = 0; e < 8; e++) row[e] = &sv[(eb + e) * 140];

    const float bd1a = __ldg(&bd1[2 * lane]), bd1b = __ldg(&bd1[2 * lane + 1]);
    const float bf1a = __ldg(&bf1[2 * lane]), bf1b = __ldg(&bf1[2 * lane + 1]);
    const float bf2a = __ldg(&bf2[2 * lane]), bf2b = __ldg(&bf2[2 * lane + 1]);
    const float bd2a = (2 * lane < 44) ? __ldg(&bd2[2 * lane]) : 0.f;
    const float bd2b = (2 * lane + 1 < 44) ? __ldg(&bd2[2 * lane + 1]) : 0.f;

    const int eq = lane >> 2, q = lane & 3;   // z-update mapping
    float* rq = row[eq];
    const int bq = eg + eq;
    const float bf3a = __ldg(&bf3[2 * q]), bf3b = __ldg(&bf3[2 * q + 1]);

    float2 zr = *(const float2*)&g_z0[bq * 8 + 2 * q];
    *(float2*)&rq[2 * q] = zr;
    __syncwarp();

    const float dt = 1.f / (float)(TT - 1);
    float sse[8];
#pragma unroll
    for (int e = 0; e < 8; e++) sse[e] = 0.f;

#pragma unroll 1
    for (int t = 0; t < TT; t++) {
        // decoder layer 1
        gemv64<2, 0>(sWd1p, row, 0, 8, bd1a, bd1b, lane);
        // decoder layer 2 + loss
        {
            u64 aA[8], aB[8];
#pragma unroll
            for (int e = 0; e < 8; e++) { aA[e] = 0ull; aB[e] = 0ull; }
#pragma unroll 2
            for (int kq = 0; kq < 16; kq++) {
                const double2 wA = *(const double2*)&sWd2p[(2 * kq) * 128 + 4 * lane];
                const double2 wB = *(const double2*)&sWd2p[(2 * kq + 1) * 128 + 4 * lane];
                const u64 w0 = d2u(wA.x), w1 = d2u(wA.y), w2 = d2u(wB.x), w3 = d2u(wB.y);
#pragma unroll
                for (int e = 0; e < 8; e++) {
                    const double2 vv = *(const double2*)&row[e][8 + 4 * kq];
                    const u64 v0 = d2u(vv.x), v1 = d2u(vv.y);
                    ffma2(aA[e], w0, v0); ffma2(aB[e], w1, v0);
                    ffma2(aA[e], w2, v1); ffma2(aB[e], w3, v1);
                }
            }
            __syncwarp();
            if (2 * lane < 44) {
#pragma unroll
                for (int e = 0; e < 8; e++) {
                    const size_t off = ((size_t)(eg + e) * TT + t) * DD + 2 * lane;
                    const float2 xv = *(const float2*)&x[off];
                    const float2 mv = *(const float2*)&mask[off];
                    const float p0 = hadd2(aA[e]) + bd2a;
                    const float p1 = hadd2(aB[e]) + bd2b;
                    float da = xv.x - p0, db = xv.y - p1;
                    da = (xv.x * mv.x != 0.f) ? 0.f : da;
                    db = (xv.y * mv.y != 0.f) ? 0.f : db;
                    sse[e] += da * da + db * db;
                }
            }
        }
        // RK4
        if (t < TT - 1) {
            float2 zac = zr;
#pragma unroll 1
            for (int s = 0; s < 4; s++) {
                const float wco = (s == 0 || s == 3) ? dt / 6.0f : dt / 3.0f;
                const float cco = (s == 2) ? dt : 0.5f * dt;
                gemv64<2, 1>(sWf1p, row, 0, 8, bf1a, bf1b, lane);
                gemv64<16, 1>(sWf2p, row, 8, 72, bf2a, bf2b, lane);
                u64 f0 = 0ull, f1 = 0ull;
#pragma unroll 8
                for (int kp = 0; kp < 32; kp++) {
                    const double2 w = *(const double2*)&sWf3p[kp * 16 + 4 * q];
                    const u64 v = d2u(*(const double*)&rq[72 + 2 * kp]);
                    ffma2(f0, d2u(w.x), v); ffma2(f1, d2u(w.y), v);
                }
                const float fa = hadd2(f0) + bf3a, fb = hadd2(f1) + bf3b;
                zac.x += wco * fa; zac.y += wco * fb;
                float2 zin;
                if (s < 3) { zin.x = zr.x + cco * fa; zin.y = zr.y + cco * fb; }
                else       { zr = zac; zin = zac; }
                *(float2*)&rq[2 * q] = zin;
                __syncwarp();
            }
        }
    }

    const float nlv = 2.0f * logf(0.3f);
    const float l2p = logf(6.283185307179586f);
#pragma unroll
    for (int e = 0; e < 8; e++) {
        float s = sse[e];
        s += __shfl_xor_sync(0xffffffffu, s, 1);
        s += __shfl_xor_sync(0xffffffffu, s, 2);
        s += __shfl_xor_sync(0xffffffffu, s, 4);
        s += __shfl_xor_sync(0xffffffffu, s, 8);
        s += __shfl_xor_sync(0xffffffffu, s, 16);
        if (lane == e) {
            const float logpx = -0.5f * ((float)(TT * DD) * (l2p + nlv) + s / expf(nlv));
            g_perb[eg + e] = -logpx + g_kl[eg + e];
        }
    }
}

// ---------------------------------------------------------------------------
__global__ void reduce_kernel(float* __restrict__ out)
{
    __shared__ float s[1024];
    const int tid = threadIdx.x;
    float v = 0.f;
    for (int i = tid; i < BB; i += 1024) v += g_perb[i];
    s[tid] = v;
    __syncthreads();
    for (int st = 512; st > 0; st >>= 1) {
        if (tid < st) s[tid] += s[tid + st];
        __syncthreads();
    }
    if (tid == 0) out[0] = s[0] / (float)BB;
}

// ---------------------------------------------------------------------------
extern "C" void kernel_launch(void* const* d_in, const int* in_sizes, int n_in,
                              void* d_out, int out_size)
{
    const float* x    = (const float*)d_in[0];
    const float* mask = (const float*)d_in[1];
    const float* eps  = (const float*)d_in[2];
    const float* Wi2h = (const float*)d_in[3];
    const float* bi2h = (const float*)d_in[4];
    const float* Wh2o = (const float*)d_in[5];
    const float* bh2o = (const float*)d_in[6];
    const float* Wf1  = (const float*)d_in[7];
    const float* bf1  = (const float*)d_in[8];
    const float* Wf2  = (const float*)d_in[9];
    const float* bf2  = (const float*)d_in[10];
    const float* Wf3  = (const float*)d_in[11];
    const float* bf3  = (const float*)d_in[12];
    const float* Wd1  = (const float*)d_in[13];
    const float* bd1  = (const float*)d_in[14];
    const float* Wd2  = (const float*)d_in[15];
    const float* bd2  = (const float*)d_in[16];

    enc_kernel<<<BB / 16, 64>>>(x, mask, eps, Wi2h, bi2h, Wh2o, bh2o);
    ode_kernel<<<BB / 16, 64>>>(x, mask, Wf1, bf1, Wf2, bf2, Wf3, bf3,
                                Wd1, bd1, Wd2, bd2);
    reduce_kernel<<<1, 1024>>>((float*)d_out);
}